// round 14
// baseline (speedup 1.0000x reference)
#include <cuda_runtime.h>
#include <cuda_bf16.h>
#include <math.h>

#define NN 50000
#define EE 800000
#define FULLMASK 0xffffffffu
typedef unsigned short ush;

// ---------------- scratch (static device memory; no allocations) ----------------
__device__ int   g_deg[NN];
__device__ int   g_pos[NN];
__device__ int   g_rowptr[NN + 1];
__device__ int   g_col[EE + NN];
__device__ float g_h1[NN * 256];
__device__ float g_x0[NN * 256];
__device__ float g_as[NN * 8];
__device__ float g_ad[NN * 8];
__device__ float g_h2[NN * 256];
__device__ float g_xs[NN * 32];
__device__ float g_h3[NN * 32];
__device__ float g_as3[NN];
__device__ float g_ad3[NN];
__device__ float g_scale1[256], g_shift1[256], g_scale2[256], g_shift2[256];
// pre-split bf16 operands
__device__ ush g_xhi[NN * 128],  g_xlo[NN * 128];
__device__ ush g_o1hi[NN * 256], g_o1lo[NN * 256];
__device__ ush g_o2hi[NN * 256], g_o2lo[NN * 256];
__device__ ush g_bt1hi[640 * 128], g_bt1lo[640 * 128];   // [W1|Ws1|va1] pad->640, K=128
__device__ ush g_bt2hi[384 * 256], g_bt2lo[384 * 256];   // [W2|Ws2|va2] pad->384, K=256
__device__ ush g_bt3hi[64 * 256],  g_bt3lo[64 * 256];    // [W3|va3]     pad->64,  K=256

__device__ __forceinline__ void split1(float f, ush& h, ush& l) {
    __nv_bfloat16 hb = __float2bfloat16(f);
    h = __bfloat16_as_ushort(hb);
    l = __bfloat16_as_ushort(__float2bfloat16(f - __bfloat162float(hb)));
}

// ---------------- CSR build ----------------
__global__ void init_deg_kernel(int* deg, int n) {
    int i = blockIdx.x * blockDim.x + threadIdx.x;
    if (i < n) deg[i] = 1;
}

__global__ void count_kernel(const int* __restrict__ dst, int e, int* __restrict__ deg) {
    int i = blockIdx.x * blockDim.x + threadIdx.x;
    if (i < e) atomicAdd(&deg[dst[i]], 1);
}

__global__ void scan_kernel(const int* __restrict__ deg, int* __restrict__ rowptr, int n) {
    __shared__ int wsum[32];
    __shared__ int s_carry;
    int tid = threadIdx.x, lane = tid & 31, wid = tid >> 5;
    if (tid == 0) { s_carry = 0; rowptr[0] = 0; }
    __syncthreads();
    for (int base = 0; base < n; base += 4096) {
        int i = base + tid * 4;
        int v0 = (i     < n) ? deg[i]     : 0;
        int v1 = (i + 1 < n) ? deg[i + 1] : 0;
        int v2 = (i + 2 < n) ? deg[i + 2] : 0;
        int v3 = (i + 3 < n) ? deg[i + 3] : 0;
        int s = v0 + v1 + v2 + v3;
        int inc = s;
#pragma unroll
        for (int off = 1; off < 32; off <<= 1) {
            int t = __shfl_up_sync(FULLMASK, inc, off);
            if (lane >= off) inc += t;
        }
        if (lane == 31) wsum[wid] = inc;
        __syncthreads();
        if (wid == 0) {
            int w = wsum[lane];
#pragma unroll
            for (int off = 1; off < 32; off <<= 1) {
                int t = __shfl_up_sync(FULLMASK, w, off);
                if (lane >= off) w += t;
            }
            wsum[lane] = w;
        }
        __syncthreads();
        int excl = s_carry + (wid ? wsum[wid - 1] : 0) + (inc - s);
        if (i     < n) rowptr[i + 1] = excl + v0;
        if (i + 1 < n) rowptr[i + 2] = excl + v0 + v1;
        if (i + 2 < n) rowptr[i + 3] = excl + v0 + v1 + v2;
        if (i + 3 < n) rowptr[i + 4] = excl + s;
        __syncthreads();
        if (tid == 0) s_carry += wsum[31];
        __syncthreads();
    }
}

__global__ void selfscatter_kernel(const int* __restrict__ rowptr, int* __restrict__ col,
                                   int* __restrict__ pos, int n) {
    int i = blockIdx.x * blockDim.x + threadIdx.x;
    if (i < n) {
        int r = rowptr[i];
        col[r] = i;
        pos[i] = r + 1;
    }
}

__global__ void scatter_kernel(const int* __restrict__ src, const int* __restrict__ dst, int e,
                               int* __restrict__ pos, int* __restrict__ col) {
    int i = blockIdx.x * blockDim.x + threadIdx.x;
    if (i < e) {
        int d = dst[i];
        int p = atomicAdd(&pos[d], 1);
        col[p] = src[i];
    }
}

// ---------------- BN fold ----------------
__global__ void bnprep_kernel(const float* b1, const float* g1, const float* be1,
                              const float* m1, const float* v1,
                              const float* b2, const float* g2, const float* be2,
                              const float* m2, const float* v2) {
    int t = threadIdx.x;
    if (t < 256) {
        float s1 = g1[t] * rsqrtf(v1[t] + 1e-5f);
        g_scale1[t] = s1;
        g_shift1[t] = be1[t] + (b1[t] - m1[t]) * s1;
        float s2 = g2[t] * rsqrtf(v2[t] + 1e-5f);
        g_scale2[t] = s2;
        g_shift2[t] = be2[t] + (b2[t] - m2[t]) * s2;
    }
}

// ---------------- pre-split converts ----------------
__global__ void convert_x_kernel(const float* __restrict__ x, ush* __restrict__ hi,
                                 ush* __restrict__ lo, int total4) {
    int i = blockIdx.x * blockDim.x + threadIdx.x;
    if (i >= total4) return;
    float4 v = *reinterpret_cast<const float4*>(x + i * 4);
    ush h[4], l[4];
    split1(v.x, h[0], l[0]); split1(v.y, h[1], l[1]);
    split1(v.z, h[2], l[2]); split1(v.w, h[3], l[3]);
    *reinterpret_cast<uint2*>(hi + i * 4) = *reinterpret_cast<uint2*>(h);
    *reinterpret_cast<uint2*>(lo + i * 4) = *reinterpret_cast<uint2*>(l);
}

// pack [B1 | B2 | v_src | v_dst]^T into [colPad][K] hi/lo.
__global__ void pack_bt_kernel(const float* __restrict__ B1, int ldb1, int w1,
                               const float* __restrict__ B2, int ldb2, int w2,
                               const float* __restrict__ aS, const float* __restrict__ aD,
                               int nha,
                               int K, int colPad, ush* __restrict__ hi, ush* __restrict__ lo) {
    int i = blockIdx.x * blockDim.x + threadIdx.x;
    if (i >= colPad * K) return;
    int c = i / K, k = i - c * K;
    float v = 0.f;
    if (c < w1) {
        v = B1[(size_t)k * ldb1 + c];
    } else if (c < w1 + w2) {
        v = B2[(size_t)k * ldb2 + (c - w1)];
    } else if (c < w1 + w2 + 2 * nha) {
        int j = c - w1 - w2;
        const float* av = (j < nha) ? aS : aD;
        int hh = j % nha;
        const float* wrow = B1 + (size_t)k * ldb1 + hh * 32;
        const float* arow = av + hh * 32;
        float s = 0.f;
#pragma unroll 8
        for (int cc = 0; cc < 32; cc++) s += wrow[cc] * arow[cc];
        v = s;
    }
    split1(v, hi[i], lo[i]);
}

// ---------------- tensor-core GEMM: 3-stage cp.async, pre-split bf16 ----------------
__device__ __forceinline__ void mma_bf16(float* c, const unsigned* a, unsigned b0, unsigned b1) {
    asm volatile(
        "mma.sync.aligned.m16n8k16.row.col.f32.bf16.bf16.f32 "
        "{%0,%1,%2,%3}, {%4,%5,%6,%7}, {%8,%9}, {%0,%1,%2,%3};"
        : "+f"(c[0]), "+f"(c[1]), "+f"(c[2]), "+f"(c[3])
        : "r"(a[0]), "r"(a[1]), "r"(a[2]), "r"(a[3]), "r"(b0), "r"(b1));
}

__device__ __forceinline__ void ldsm_x4(unsigned* r, unsigned addr) {
    asm volatile("ldmatrix.sync.aligned.m8n8.x4.shared.b16 {%0,%1,%2,%3}, [%4];"
                 : "=r"(r[0]), "=r"(r[1]), "=r"(r[2]), "=r"(r[3]) : "r"(addr));
}

__device__ __forceinline__ void cpa16(unsigned dst, const void* src, bool valid) {
    int sz = valid ? 16 : 0;
    asm volatile("cp.async.cg.shared.global [%0], [%1], 16, %2;"
                 :: "r"(dst), "l"(src), "r"(sz));
}
__device__ __forceinline__ void cpa_commit() {
    asm volatile("cp.async.commit_group;" ::: "memory");
}
template <int Nw>
__device__ __forceinline__ void cpa_wait() {
    asm volatile("cp.async.wait_group %0;" :: "n"(Nw) : "memory");
}

// row layout: 128B/row, 8x16B chunks (0-3 hi k0..31, 4-7 lo). phys = chunk ^ (row&7)
__device__ __forceinline__ unsigned swz(unsigned base, int row, int chunk) {
    return base + row * 128 + ((chunk ^ (row & 7)) << 4);
}

// C = A @ [B1|B2|vS|vD]. Cols bnbase + blockIdx.x*BN. Routing per column-pair.
template <int BN>
__global__ void __launch_bounds__(256, 2)
mma_gemm_kernel(const ush* __restrict__ Ahi, const ush* __restrict__ Alo, int M, int K,
                const ush* __restrict__ Bthi, const ush* __restrict__ Btlo,
                int bnbase,
                int split, int aoff, int nha,
                float* __restrict__ C1, int ldc1,
                float* __restrict__ C2, int ldc2,
                const float* __restrict__ bias2,
                float* __restrict__ aso, float* __restrict__ ado) {
    constexpr int NFR   = BN / 16;
    constexpr int NP    = BN / 32;
    constexpr int STAGE = (128 + BN) * 128;
    extern __shared__ __align__(16) unsigned char smem[];
    const unsigned sbase = (unsigned)__cvta_generic_to_shared(smem);

    const int tid  = threadIdx.x;
    const int lane = tid & 31, warp = tid >> 5;
    const int wm = (warp & 3) * 32;
    const int wn = (warp >> 2) * (BN / 2);
    const int g  = lane >> 2, t2 = (lane & 3) * 2;
    const int bm = blockIdx.y * 128, bn = bnbase + blockIdx.x * BN;
    const int lrow = lane & 15, lchk = lane >> 4;

    const int r = tid >> 1, half = tid & 1;
    const int gr = bm + r;
    const bool av = gr < M;
    const bool bv = tid < 2 * BN;
    const ush* aH = Ahi + (size_t)(av ? gr : 0) * K + half * 16;
    const ush* aL = Alo + (size_t)(av ? gr : 0) * K + half * 16;
    const ush* bH = Bthi + (size_t)(bn + (bv ? r : 0)) * K + half * 16;
    const ush* bL = Btlo + (size_t)(bn + (bv ? r : 0)) * K + half * 16;
    const int c0 = half * 2;

    float acc[2][NFR][4];
#pragma unroll
    for (int mf = 0; mf < 2; mf++)
#pragma unroll
        for (int nf = 0; nf < NFR; nf++)
#pragma unroll
            for (int q = 0; q < 4; q++) acc[mf][nf][q] = 0.f;

    const int niter = K >> 5;

#pragma unroll
    for (int pstg = 0; pstg < 2; pstg++) {
        if (pstg < niter) {
            int k0 = pstg << 5;
            unsigned aB = sbase + pstg * STAGE, bB = aB + 16384;
            cpa16(swz(aB, r, c0 + 0), aH + k0, av);     cpa16(swz(aB, r, c0 + 1), aH + k0 + 8, av);
            cpa16(swz(aB, r, c0 + 4), aL + k0, av);     cpa16(swz(aB, r, c0 + 5), aL + k0 + 8, av);
            if (bv) {
                cpa16(swz(bB, r, c0 + 0), bH + k0, true);   cpa16(swz(bB, r, c0 + 1), bH + k0 + 8, true);
                cpa16(swz(bB, r, c0 + 4), bL + k0, true);   cpa16(swz(bB, r, c0 + 5), bL + k0 + 8, true);
            }
        }
        cpa_commit();
    }

    int st = 0;
    for (int i = 0; i < niter; i++) {
        cpa_wait<1>();
        __syncthreads();
        int stw = st + 2; if (stw >= 3) stw -= 3;
        if (i + 2 < niter) {
            int k0 = (i + 2) << 5;
            unsigned aB = sbase + stw * STAGE, bB = aB + 16384;
            cpa16(swz(aB, r, c0 + 0), aH + k0, av);     cpa16(swz(aB, r, c0 + 1), aH + k0 + 8, av);
            cpa16(swz(aB, r, c0 + 4), aL + k0, av);     cpa16(swz(aB, r, c0 + 5), aL + k0 + 8, av);
            if (bv) {
                cpa16(swz(bB, r, c0 + 0), bH + k0, true);   cpa16(swz(bB, r, c0 + 1), bH + k0 + 8, true);
                cpa16(swz(bB, r, c0 + 4), bL + k0, true);   cpa16(swz(bB, r, c0 + 5), bL + k0 + 8, true);
            }
        }
        cpa_commit();

        const unsigned sA = sbase + st * STAGE, sB = sA + 16384;
#pragma unroll
        for (int ks = 0; ks < 2; ks++) {
            const int kc = ks * 2 + lchk;
            unsigned ah[2][4], al[2][4];
#pragma unroll
            for (int mf = 0; mf < 2; mf++) {
                int row = wm + mf * 16 + lrow;
                ldsm_x4(ah[mf], swz(sA, row, kc));
                ldsm_x4(al[mf], swz(sA, row, kc + 4));
            }
#pragma unroll
            for (int p = 0; p < NP; p++) {
                int row = wn + p * 16 + lrow;
                unsigned bh[4], bl[4];
                ldsm_x4(bh, swz(sB, row, kc));
                ldsm_x4(bl, swz(sB, row, kc + 4));
#pragma unroll
                for (int mf = 0; mf < 2; mf++) {
                    mma_bf16(acc[mf][2 * p],     ah[mf], bh[0], bh[2]);
                    mma_bf16(acc[mf][2 * p],     al[mf], bh[0], bh[2]);
                    mma_bf16(acc[mf][2 * p],     ah[mf], bl[0], bl[2]);
                    mma_bf16(acc[mf][2 * p + 1], ah[mf], bh[1], bh[3]);
                    mma_bf16(acc[mf][2 * p + 1], al[mf], bh[1], bh[3]);
                    mma_bf16(acc[mf][2 * p + 1], ah[mf], bl[1], bl[3]);
                }
            }
        }
        st = (st + 1 == 3) ? 0 : st + 1;
    }

    // epilogue: column pairs (cc even) never straddle the even split/aoff
    // boundaries -> vectorized STG.64 for C1/C2; scalar fallback for alpha.
#pragma unroll
    for (int mf = 0; mf < 2; mf++) {
#pragma unroll
        for (int halfq = 0; halfq < 2; halfq++) {
            int rr = bm + wm + mf * 16 + g + halfq * 8;
            if (rr >= M) continue;
#pragma unroll
            for (int nf = 0; nf < NFR; nf++) {
                int cc = bn + wn + nf * 8 + t2;
                float v0 = acc[mf][nf][halfq * 2 + 0];
                float v1 = acc[mf][nf][halfq * 2 + 1];
                if (cc < split) {
                    *reinterpret_cast<float2*>(&C1[(size_t)rr * ldc1 + cc]) =
                        make_float2(v0, v1);
                } else if (cc < aoff) {
                    int c2 = cc - split;
                    if (bias2) { v0 += bias2[c2]; v1 += bias2[c2 + 1]; }
                    *reinterpret_cast<float2*>(&C2[(size_t)rr * ldc2 + c2]) =
                        make_float2(v0, v1);
                } else {
#pragma unroll
                    for (int q = 0; q < 2; q++) {
                        int c = cc + q;
                        float v = (q == 0) ? v0 : v1;
                        if (c < aoff + nha) {
                            aso[(size_t)rr * nha + (c - aoff)] = v;
                        } else if (c < aoff + 2 * nha) {
                            ado[(size_t)rr * nha + (c - aoff - nha)] = v;
                        }
                    }
                }
            }
        }
    }
}

// ---------------- 8-head aggregation (2-edge unrolled) + BN/ELU/skip; emits hi/lo bf16 ----------------
__global__ void agg8_kernel(const float* __restrict__ h,
                            const float* __restrict__ as_, const float* __restrict__ ad_,
                            const int* __restrict__ rowptr, const int* __restrict__ col,
                            const float* __restrict__ scale, const float* __restrict__ shift,
                            const float* __restrict__ skip,
                            ush* __restrict__ outhi, ush* __restrict__ outlo, int n) {
    int node = (blockIdx.x * blockDim.x + threadIdx.x) >> 5;
    if (node >= n) return;
    int lane = threadIdx.x & 31;
    int hd8 = lane & 7;
    int wsrc = lane >> 2;
    float adv = ad_[(size_t)node * 8 + hd8];
    int start = rowptr[node], end = rowptr[node + 1];
    float acc[8];
#pragma unroll
    for (int i = 0; i < 8; i++) acc[i] = 0.f;
    float denom = 0.f;

    int sA = __ldg(&col[start]);
    float lA = __ldg(&as_[(size_t)sA * 8 + hd8]);
    int sB = 0; float lB = 0.f;
    if (start + 1 < end) {
        sB = __ldg(&col[start + 1]);
        lB = __ldg(&as_[(size_t)sB * 8 + hd8]);
    }
    for (int j = start; j < end; j += 2) {
        int s0 = sA; float e0 = lA;
        bool two = (j + 1 < end);
        int s1 = sB; float e1 = lB;
        if (j + 2 < end) {
            sA = __ldg(&col[j + 2]);
            lA = __ldg(&as_[(size_t)sA * 8 + hd8]);
        }
        if (j + 3 < end) {
            sB = __ldg(&col[j + 3]);
            lB = __ldg(&as_[(size_t)sB * 8 + hd8]);
        }
        e0 += adv; e0 = e0 > 0.f ? e0 : 0.2f * e0;
        float w0 = __expf(e0);
        denom += w0;
        float wh0 = __shfl_sync(FULLMASK, w0, wsrc);
        const float4* hp0 = reinterpret_cast<const float4*>(h + (size_t)s0 * 256 + lane * 8);
        float4 v00 = __ldcg(hp0), v01 = __ldcg(hp0 + 1);
        if (two) {
            e1 += adv; e1 = e1 > 0.f ? e1 : 0.2f * e1;
            float w1 = __expf(e1);
            denom += w1;
            float wh1 = __shfl_sync(FULLMASK, w1, wsrc);
            const float4* hp1 = reinterpret_cast<const float4*>(h + (size_t)s1 * 256 + lane * 8);
            float4 v10 = __ldcg(hp1), v11 = __ldcg(hp1 + 1);
            acc[0] = fmaf(wh0, v00.x, acc[0]); acc[1] = fmaf(wh0, v00.y, acc[1]);
            acc[2] = fmaf(wh0, v00.z, acc[2]); acc[3] = fmaf(wh0, v00.w, acc[3]);
            acc[4] = fmaf(wh0, v01.x, acc[4]); acc[5] = fmaf(wh0, v01.y, acc[5]);
            acc[6] = fmaf(wh0, v01.z, acc[6]); acc[7] = fmaf(wh0, v01.w, acc[7]);
            acc[0] = fmaf(wh1, v10.x, acc[0]); acc[1] = fmaf(wh1, v10.y, acc[1]);
            acc[2] = fmaf(wh1, v10.z, acc[2]); acc[3] = fmaf(wh1, v10.w, acc[3]);
            acc[4] = fmaf(wh1, v11.x, acc[4]); acc[5] = fmaf(wh1, v11.y, acc[5]);
            acc[6] = fmaf(wh1, v11.z, acc[6]); acc[7] = fmaf(wh1, v11.w, acc[7]);
        } else {
            acc[0] = fmaf(wh0, v00.x, acc[0]); acc[1] = fmaf(wh0, v00.y, acc[1]);
            acc[2] = fmaf(wh0, v00.z, acc[2]); acc[3] = fmaf(wh0, v00.w, acc[3]);
            acc[4] = fmaf(wh0, v01.x, acc[4]); acc[5] = fmaf(wh0, v01.y, acc[5]);
            acc[6] = fmaf(wh0, v01.z, acc[6]); acc[7] = fmaf(wh0, v01.w, acc[7]);
        }
    }
    float dh = __shfl_sync(FULLMASK, denom, wsrc) + 1e-16f;
    float inv = 1.f / dh;
    int chb = lane * 8;
    float4 s0v, s1v;
    if (skip) {
        const float4* sp = reinterpret_cast<const float4*>(skip + (size_t)node * 256 + chb);
        s0v = __ldcg(sp); s1v = __ldcg(sp + 1);
    } else {
        s0v = make_float4(0.f, 0.f, 0.f, 0.f); s1v = s0v;
    }
    float sk[8] = {s0v.x, s0v.y, s0v.z, s0v.w, s1v.x, s1v.y, s1v.z, s1v.w};
    ush hv[8], lv[8];
#pragma unroll
    for (int j = 0; j < 8; j++) {
        int ch = chb + j;
        float y = acc[j] * inv;
        y = y * scale[ch] + shift[ch];
        y = y > 0.f ? y : expm1f(y);
        y += sk[j];
        split1(y, hv[j], lv[j]);
    }
    *reinterpret_cast<uint4*>(outhi + (size_t)node * 256 + chb) = *reinterpret_cast<uint4*>(hv);
    *reinterpret_cast<uint4*>(outlo + (size_t)node * 256 + chb) = *reinterpret_cast<uint4*>(lv);
}

// ---------------- 1-head final aggregation (2-edge unrolled) + bias + skip ----------------
__global__ void agg1_kernel(const float* __restrict__ h3,
                            const float* __restrict__ as3, const float* __restrict__ ad3,
                            const int* __restrict__ rowptr, const int* __restrict__ col,
                            const float* __restrict__ b3, const float* __restrict__ xs,
                            float* __restrict__ out, int n) {
    int node = (blockIdx.x * blockDim.x + threadIdx.x) >> 5;
    if (node >= n) return;
    int lane = threadIdx.x & 31;
    float adv = ad3[node];
    int start = rowptr[node], end = rowptr[node + 1];
    float acc = 0.f, denom = 0.f;

    int sA = __ldg(&col[start]);
    float lA = __ldg(&as3[sA]);
    int sB = 0; float lB = 0.f;
    if (start + 1 < end) {
        sB = __ldg(&col[start + 1]);
        lB = __ldg(&as3[sB]);
    }
    for (int j = start; j < end; j += 2) {
        int s0 = sA; float e0 = lA;
        bool two = (j + 1 < end);
        int s1 = sB; float e1 = lB;
        if (j + 2 < end) {
            sA = __ldg(&col[j + 2]);
            lA = __ldg(&as3[sA]);
        }
        if (j + 3 < end) {
            sB = __ldg(&col[j + 3]);
            lB = __ldg(&as3[sB]);
        }
        e0 += adv; e0 = e0 > 0.f ? e0 : 0.2f * e0;
        float w0 = __expf(e0);
        denom += w0;
        float hv0 = __ldcg(&h3[(size_t)s0 * 32 + lane]);
        if (two) {
            e1 += adv; e1 = e1 > 0.f ? e1 : 0.2f * e1;
            float w1 = __expf(e1);
            denom += w1;
            float hv1 = __ldcg(&h3[(size_t)s1 * 32 + lane]);
            acc = fmaf(w0, hv0, acc);
            acc = fmaf(w1, hv1, acc);
        } else {
            acc = fmaf(w0, hv0, acc);
        }
    }
    out[(size_t)node * 32 + lane] = acc / (denom + 1e-16f) + b3[lane] + xs[(size_t)node * 32 + lane];
}

// ---------------- host launcher (R11 structure, verbatim) ----------------
#define GSYM(ptr, sym) do { void* _t; cudaGetSymbolAddress(&_t, sym); ptr = (decltype(ptr))_t; } while (0)

extern "C" void kernel_launch(void* const* d_in, const int* in_sizes, int n_in,
                              void* d_out, int out_size) {
    const float* x      = (const float*)d_in[0];
    const int*   ei     = (const int*)d_in[1];
    const float* W1     = (const float*)d_in[2];
    const float* a_src1 = (const float*)d_in[3];
    const float* a_dst1 = (const float*)d_in[4];
    const float* b1     = (const float*)d_in[5];
    const float* bn1_g  = (const float*)d_in[6];
    const float* bn1_b  = (const float*)d_in[7];
    const float* bn1_m  = (const float*)d_in[8];
    const float* bn1_v  = (const float*)d_in[9];
    const float* W2     = (const float*)d_in[10];
    const float* a_src2 = (const float*)d_in[11];
    const float* a_dst2 = (const float*)d_in[12];
    const float* b2     = (const float*)d_in[13];
    const float* bn2_g  = (const float*)d_in[14];
    const float* bn2_b  = (const float*)d_in[15];
    const float* bn2_m  = (const float*)d_in[16];
    const float* bn2_v  = (const float*)d_in[17];
    const float* W3     = (const float*)d_in[18];
    const float* a_src3 = (const float*)d_in[19];
    const float* a_dst3 = (const float*)d_in[20];
    const float* b3     = (const float*)d_in[21];
    const float* Ws1    = (const float*)d_in[22];
    const float* bs1    = (const float*)d_in[23];
    const float* Ws2    = (const float*)d_in[24];
    const float* bs2    = (const float*)d_in[25];

    const int N = in_sizes[0] / 128;
    const int E = in_sizes[1] / 2;
    const int* srcp = ei;
    const int* dstp = ei + E;

    int *deg, *pos, *rowptr, *col;
    float *h1, *x0, *as_, *ad_, *h2, *xs, *h3, *as3, *ad3;
    float *scale1, *shift1, *scale2, *shift2;
    ush *xhi, *xlo, *o1hi, *o1lo, *o2hi, *o2lo;
    ush *bt1hi, *bt1lo, *bt2hi, *bt2lo, *bt3hi, *bt3lo;
    GSYM(deg, g_deg); GSYM(pos, g_pos); GSYM(rowptr, g_rowptr); GSYM(col, g_col);
    GSYM(h1, g_h1); GSYM(x0, g_x0); GSYM(as_, g_as); GSYM(ad_, g_ad);
    GSYM(h2, g_h2); GSYM(xs, g_xs); GSYM(h3, g_h3); GSYM(as3, g_as3); GSYM(ad3, g_ad3);
    GSYM(scale1, g_scale1); GSYM(shift1, g_shift1);
    GSYM(scale2, g_scale2); GSYM(shift2, g_shift2);
    GSYM(xhi, g_xhi); GSYM(xlo, g_xlo);
    GSYM(o1hi, g_o1hi); GSYM(o1lo, g_o1lo); GSYM(o2hi, g_o2hi); GSYM(o2lo, g_o2lo);
    GSYM(bt1hi, g_bt1hi); GSYM(bt1lo, g_bt1lo);
    GSYM(bt2hi, g_bt2hi); GSYM(bt2lo, g_bt2lo);
    GSYM(bt3hi, g_bt3hi); GSYM(bt3lo, g_bt3lo);

    static cudaStream_t s2 = 0;
    static cudaEvent_t evFork = 0, evP1 = 0, evJ1 = 0, evO1 = 0, evJ2 = 0;
    static bool inited = false;
    if (!inited) {
        cudaFuncSetAttribute(mma_gemm_kernel<128>,
                             cudaFuncAttributeMaxDynamicSharedMemorySize, 3 * 256 * 128);
        cudaFuncSetAttribute(mma_gemm_kernel<64>,
                             cudaFuncAttributeMaxDynamicSharedMemorySize, 3 * 192 * 128);
        cudaStreamCreateWithFlags(&s2, cudaStreamNonBlocking);
        cudaEventCreateWithFlags(&evFork, cudaEventDisableTiming);
        cudaEventCreateWithFlags(&evP1, cudaEventDisableTiming);
        cudaEventCreateWithFlags(&evJ1, cudaEventDisableTiming);
        cudaEventCreateWithFlags(&evO1, cudaEventDisableTiming);
        cudaEventCreateWithFlags(&evJ2, cudaEventDisableTiming);
        inited = true;
    }

    const int TB = 256;
    const int nb_N  = (N + TB - 1) / TB;
    const int nb_E  = (E + TB - 1) / TB;
    const int nb_W  = (N * 32 + TB - 1) / TB;
    const int gy    = (N + 127) / 128;

    // ---- fork ----
    cudaEventRecord(evFork, 0);
    cudaStreamWaitEvent(s2, evFork, 0);

    // side stream: CSR + bnprep + packs 2/3
    init_deg_kernel<<<nb_N, TB, 0, s2>>>(deg, N);
    count_kernel<<<nb_E, TB, 0, s2>>>(dstp, E, deg);
    scan_kernel<<<1, 1024, 0, s2>>>(deg, rowptr, N);
    selfscatter_kernel<<<nb_N, TB, 0, s2>>>(rowptr, col, pos, N);
    scatter_kernel<<<nb_E, TB, 0, s2>>>(srcp, dstp, E, pos, col);
    bnprep_kernel<<<1, 256, 0, s2>>>(b1, bn1_g, bn1_b, bn1_m, bn1_v,
                                     b2, bn2_g, bn2_b, bn2_m, bn2_v);
    pack_bt_kernel<<<(384 * 256 + TB - 1) / TB, TB, 0, s2>>>(W2, 256, 256, Ws2, 32, 32,
                                                             a_src2, a_dst2, 8, 256, 384, bt2hi, bt2lo);
    pack_bt_kernel<<<(64 * 256 + TB - 1) / TB, TB, 0, s2>>>(W3, 32, 32, W3, 32, 0,
                                                            a_src3, a_dst3, 1, 256, 64, bt3hi, bt3lo);

    // main: converts + pack1
    convert_x_kernel<<<(N * 128 / 4 + TB - 1) / TB, TB>>>(x, xhi, xlo, N * 128 / 4);
    pack_bt_kernel<<<(640 * 128 + TB - 1) / TB, TB>>>(W1, 256, 256, Ws1, 256, 256,
                                                      a_src1, a_dst1, 8, 128, 640, bt1hi, bt1lo);
    cudaEventRecord(evP1, 0);

    // GEMM1 main (h1 | x0+bs1), tail (alpha1) overlapped on s2
    mma_gemm_kernel<128><<<dim3(4, gy), TB, 3 * 256 * 128>>>(xhi, xlo, N, 128, bt1hi, bt1lo,
                                                             0, 256, 512, 8,
                                                             h1, 256, x0, 256, bs1, as_, ad_);
    cudaStreamWaitEvent(s2, evP1, 0);
    mma_gemm_kernel<64><<<dim3(1, gy), TB, 3 * 192 * 128, s2>>>(xhi, xlo, N, 128, bt1hi, bt1lo,
                                                                512, 0, 512, 8,
                                                                h1, 256, x0, 256, bs1, as_, ad_);
    cudaEventRecord(evJ1, s2);
    cudaStreamWaitEvent(0, evJ1, 0);

    // layer-1 aggregation
    agg8_kernel<<<nb_W, TB>>>(h1, as_, ad_, rowptr, col, scale1, shift1, x0, o1hi, o1lo, N);
    cudaEventRecord(evO1, 0);

    // GEMM2 main (h2 cols 0-255); tail (xs + alpha2) on s2 overlapped
    mma_gemm_kernel<128><<<dim3(2, gy), TB, 3 * 256 * 128>>>(o1hi, o1lo, N, 256, bt2hi, bt2lo,
                                                             0, 256, 288, 8,
                                                             h2, 256, xs, 32, bs2, as_, ad_);
    cudaStreamWaitEvent(s2, evO1, 0);
    mma_gemm_kernel<64><<<dim3(1, gy), TB, 3 * 192 * 128, s2>>>(o1hi, o1lo, N, 256, bt2hi, bt2lo,
                                                                256, 256, 288, 8,
                                                                h2, 256, xs, 32, bs2, as_, ad_);
    cudaEventRecord(evJ2, s2);
    cudaStreamWaitEvent(0, evJ2, 0);

    agg8_kernel<<<nb_W, TB>>>(h2, as_, ad_, rowptr, col, scale2, shift2, nullptr, o2hi, o2lo, N);

    // layer 3 (h3 | alpha_s3 | alpha_d3), narrow BN=64 tile
    mma_gemm_kernel<64><<<dim3(1, gy), TB, 3 * 192 * 128>>>(o2hi, o2lo, N, 256, bt3hi, bt3lo,
                                                            0, 32, 32, 1,
                                                            h3, 32, h3, 32, nullptr, as3, ad3);
    agg1_kernel<<<nb_W, TB>>>(h3, as3, ad3, rowptr, col, b3, xs, (float*)d_out, N);
}

// round 15
// speedup vs baseline: 1.4595x; 1.4595x over previous
#include <cuda_runtime.h>
#include <cuda_bf16.h>
#include <math.h>

#define NN 50000
#define EE 800000
#define FULLMASK 0xffffffffu
typedef unsigned short ush;

// ---------------- scratch (static device memory; no allocations) ----------------
__device__ int   g_deg[NN];
__device__ int   g_pos[NN];
__device__ int   g_rowptr[NN + 1];
__device__ int   g_col[EE + NN];
__device__ float g_h1[NN * 256];
__device__ float g_x0[NN * 256];
__device__ float g_as[NN * 8];
__device__ float g_ad[NN * 8];
__device__ float g_h2[NN * 256];
__device__ float g_xs[NN * 32];
__device__ float g_h3[NN * 32];
__device__ float g_as3[NN];
__device__ float g_ad3[NN];
__device__ float g_scale1[256], g_shift1[256], g_scale2[256], g_shift2[256];
// pre-split bf16 operands
__device__ ush g_xhi[NN * 128],  g_xlo[NN * 128];
__device__ ush g_o1hi[NN * 256], g_o1lo[NN * 256];
__device__ ush g_o2hi[NN * 256], g_o2lo[NN * 256];
__device__ ush g_bt1hi[640 * 128], g_bt1lo[640 * 128];   // [W1|Ws1|va1] pad->640, K=128
__device__ ush g_bt2hi[384 * 256], g_bt2lo[384 * 256];   // [W2|Ws2|va2] pad->384, K=256
__device__ ush g_bt3hi[64 * 256],  g_bt3lo[64 * 256];    // [W3|va3]     pad->64,  K=256

__device__ __forceinline__ void split1(float f, ush& h, ush& l) {
    __nv_bfloat16 hb = __float2bfloat16(f);
    h = __bfloat16_as_ushort(hb);
    l = __bfloat16_as_ushort(__float2bfloat16(f - __bfloat162float(hb)));
}

// ---------------- CSR build ----------------
__global__ void init_deg_kernel(int* deg, int n) {
    int i = blockIdx.x * blockDim.x + threadIdx.x;
    if (i < n) deg[i] = 1;
}

__global__ void count_kernel(const int* __restrict__ dst, int e, int* __restrict__ deg) {
    int i = blockIdx.x * blockDim.x + threadIdx.x;
    if (i < e) atomicAdd(&deg[dst[i]], 1);
}

__global__ void scan_kernel(const int* __restrict__ deg, int* __restrict__ rowptr, int n) {
    __shared__ int wsum[32];
    __shared__ int s_carry;
    int tid = threadIdx.x, lane = tid & 31, wid = tid >> 5;
    if (tid == 0) { s_carry = 0; rowptr[0] = 0; }
    __syncthreads();
    for (int base = 0; base < n; base += 4096) {
        int i = base + tid * 4;
        int v0 = (i     < n) ? deg[i]     : 0;
        int v1 = (i + 1 < n) ? deg[i + 1] : 0;
        int v2 = (i + 2 < n) ? deg[i + 2] : 0;
        int v3 = (i + 3 < n) ? deg[i + 3] : 0;
        int s = v0 + v1 + v2 + v3;
        int inc = s;
#pragma unroll
        for (int off = 1; off < 32; off <<= 1) {
            int t = __shfl_up_sync(FULLMASK, inc, off);
            if (lane >= off) inc += t;
        }
        if (lane == 31) wsum[wid] = inc;
        __syncthreads();
        if (wid == 0) {
            int w = wsum[lane];
#pragma unroll
            for (int off = 1; off < 32; off <<= 1) {
                int t = __shfl_up_sync(FULLMASK, w, off);
                if (lane >= off) w += t;
            }
            wsum[lane] = w;
        }
        __syncthreads();
        int excl = s_carry + (wid ? wsum[wid - 1] : 0) + (inc - s);
        if (i     < n) rowptr[i + 1] = excl + v0;
        if (i + 1 < n) rowptr[i + 2] = excl + v0 + v1;
        if (i + 2 < n) rowptr[i + 3] = excl + v0 + v1 + v2;
        if (i + 3 < n) rowptr[i + 4] = excl + s;
        __syncthreads();
        if (tid == 0) s_carry += wsum[31];
        __syncthreads();
    }
}

__global__ void selfscatter_kernel(const int* __restrict__ rowptr, int* __restrict__ col,
                                   int* __restrict__ pos, int n) {
    int i = blockIdx.x * blockDim.x + threadIdx.x;
    if (i < n) {
        int r = rowptr[i];
        col[r] = i;
        pos[i] = r + 1;
    }
}

__global__ void scatter_kernel(const int* __restrict__ src, const int* __restrict__ dst, int e,
                               int* __restrict__ pos, int* __restrict__ col) {
    int i = blockIdx.x * blockDim.x + threadIdx.x;
    if (i < e) {
        int d = dst[i];
        int p = atomicAdd(&pos[d], 1);
        col[p] = src[i];
    }
}

// ---------------- BN fold ----------------
__global__ void bnprep_kernel(const float* b1, const float* g1, const float* be1,
                              const float* m1, const float* v1,
                              const float* b2, const float* g2, const float* be2,
                              const float* m2, const float* v2) {
    int t = threadIdx.x;
    if (t < 256) {
        float s1 = g1[t] * rsqrtf(v1[t] + 1e-5f);
        g_scale1[t] = s1;
        g_shift1[t] = be1[t] + (b1[t] - m1[t]) * s1;
        float s2 = g2[t] * rsqrtf(v2[t] + 1e-5f);
        g_scale2[t] = s2;
        g_shift2[t] = be2[t] + (b2[t] - m2[t]) * s2;
    }
}

// ---------------- pre-split converts ----------------
__global__ void convert_x_kernel(const float* __restrict__ x, ush* __restrict__ hi,
                                 ush* __restrict__ lo, int total4) {
    int i = blockIdx.x * blockDim.x + threadIdx.x;
    if (i >= total4) return;
    float4 v = *reinterpret_cast<const float4*>(x + i * 4);
    ush h[4], l[4];
    split1(v.x, h[0], l[0]); split1(v.y, h[1], l[1]);
    split1(v.z, h[2], l[2]); split1(v.w, h[3], l[3]);
    *reinterpret_cast<uint2*>(hi + i * 4) = *reinterpret_cast<uint2*>(h);
    *reinterpret_cast<uint2*>(lo + i * 4) = *reinterpret_cast<uint2*>(l);
}

// pack [B1 | B2 | v_src | v_dst]^T into [colPad][K] hi/lo.
__global__ void pack_bt_kernel(const float* __restrict__ B1, int ldb1, int w1,
                               const float* __restrict__ B2, int ldb2, int w2,
                               const float* __restrict__ aS, const float* __restrict__ aD,
                               int nha,
                               int K, int colPad, ush* __restrict__ hi, ush* __restrict__ lo) {
    int i = blockIdx.x * blockDim.x + threadIdx.x;
    if (i >= colPad * K) return;
    int c = i / K, k = i - c * K;
    float v = 0.f;
    if (c < w1) {
        v = B1[(size_t)k * ldb1 + c];
    } else if (c < w1 + w2) {
        v = B2[(size_t)k * ldb2 + (c - w1)];
    } else if (c < w1 + w2 + 2 * nha) {
        int j = c - w1 - w2;
        const float* av = (j < nha) ? aS : aD;
        int hh = j % nha;
        const float* wrow = B1 + (size_t)k * ldb1 + hh * 32;
        const float* arow = av + hh * 32;
        float s = 0.f;
#pragma unroll 8
        for (int cc = 0; cc < 32; cc++) s += wrow[cc] * arow[cc];
        v = s;
    }
    split1(v, hi[i], lo[i]);
}

// ---------------- tensor-core GEMM: 3-stage cp.async, pre-split bf16 ----------------
__device__ __forceinline__ void mma_bf16(float* c, const unsigned* a, unsigned b0, unsigned b1) {
    asm volatile(
        "mma.sync.aligned.m16n8k16.row.col.f32.bf16.bf16.f32 "
        "{%0,%1,%2,%3}, {%4,%5,%6,%7}, {%8,%9}, {%0,%1,%2,%3};"
        : "+f"(c[0]), "+f"(c[1]), "+f"(c[2]), "+f"(c[3])
        : "r"(a[0]), "r"(a[1]), "r"(a[2]), "r"(a[3]), "r"(b0), "r"(b1));
}

__device__ __forceinline__ void ldsm_x4(unsigned* r, unsigned addr) {
    asm volatile("ldmatrix.sync.aligned.m8n8.x4.shared.b16 {%0,%1,%2,%3}, [%4];"
                 : "=r"(r[0]), "=r"(r[1]), "=r"(r[2]), "=r"(r[3]) : "r"(addr));
}

__device__ __forceinline__ void cpa16(unsigned dst, const void* src, bool valid) {
    int sz = valid ? 16 : 0;
    asm volatile("cp.async.cg.shared.global [%0], [%1], 16, %2;"
                 :: "r"(dst), "l"(src), "r"(sz));
}
__device__ __forceinline__ void cpa_commit() {
    asm volatile("cp.async.commit_group;" ::: "memory");
}
template <int Nw>
__device__ __forceinline__ void cpa_wait() {
    asm volatile("cp.async.wait_group %0;" :: "n"(Nw) : "memory");
}

// row layout: 128B/row, 8x16B chunks (0-3 hi k0..31, 4-7 lo). phys = chunk ^ (row&7)
__device__ __forceinline__ unsigned swz(unsigned base, int row, int chunk) {
    return base + row * 128 + ((chunk ^ (row & 7)) << 4);
}

// C = A @ [B1|B2|vS|vD]. Cols bnbase + blockIdx.x*BN. Routing per column-pair.
template <int BN>
__global__ void __launch_bounds__(256, 2)
mma_gemm_kernel(const ush* __restrict__ Ahi, const ush* __restrict__ Alo, int M, int K,
                const ush* __restrict__ Bthi, const ush* __restrict__ Btlo,
                int bnbase,
                int split, int aoff, int nha,
                float* __restrict__ C1, int ldc1,
                float* __restrict__ C2, int ldc2,
                const float* __restrict__ bias2,
                float* __restrict__ aso, float* __restrict__ ado) {
    constexpr int NFR   = BN / 16;
    constexpr int NP    = BN / 32;
    constexpr int STAGE = (128 + BN) * 128;
    extern __shared__ __align__(16) unsigned char smem[];
    const unsigned sbase = (unsigned)__cvta_generic_to_shared(smem);

    const int tid  = threadIdx.x;
    const int lane = tid & 31, warp = tid >> 5;
    const int wm = (warp & 3) * 32;
    const int wn = (warp >> 2) * (BN / 2);
    const int g  = lane >> 2, t2 = (lane & 3) * 2;
    const int bm = blockIdx.y * 128, bn = bnbase + blockIdx.x * BN;
    const int lrow = lane & 15, lchk = lane >> 4;

    const int r = tid >> 1, half = tid & 1;
    const int gr = bm + r;
    const bool av = gr < M;
    const bool bv = tid < 2 * BN;
    const ush* aH = Ahi + (size_t)(av ? gr : 0) * K + half * 16;
    const ush* aL = Alo + (size_t)(av ? gr : 0) * K + half * 16;
    const ush* bH = Bthi + (size_t)(bn + (bv ? r : 0)) * K + half * 16;
    const ush* bL = Btlo + (size_t)(bn + (bv ? r : 0)) * K + half * 16;
    const int c0 = half * 2;

    float acc[2][NFR][4];
#pragma unroll
    for (int mf = 0; mf < 2; mf++)
#pragma unroll
        for (int nf = 0; nf < NFR; nf++)
#pragma unroll
            for (int q = 0; q < 4; q++) acc[mf][nf][q] = 0.f;

    const int niter = K >> 5;

#pragma unroll
    for (int pstg = 0; pstg < 2; pstg++) {
        if (pstg < niter) {
            int k0 = pstg << 5;
            unsigned aB = sbase + pstg * STAGE, bB = aB + 16384;
            cpa16(swz(aB, r, c0 + 0), aH + k0, av);     cpa16(swz(aB, r, c0 + 1), aH + k0 + 8, av);
            cpa16(swz(aB, r, c0 + 4), aL + k0, av);     cpa16(swz(aB, r, c0 + 5), aL + k0 + 8, av);
            if (bv) {
                cpa16(swz(bB, r, c0 + 0), bH + k0, true);   cpa16(swz(bB, r, c0 + 1), bH + k0 + 8, true);
                cpa16(swz(bB, r, c0 + 4), bL + k0, true);   cpa16(swz(bB, r, c0 + 5), bL + k0 + 8, true);
            }
        }
        cpa_commit();
    }

    int st = 0;
    for (int i = 0; i < niter; i++) {
        cpa_wait<1>();
        __syncthreads();
        int stw = st + 2; if (stw >= 3) stw -= 3;
        if (i + 2 < niter) {
            int k0 = (i + 2) << 5;
            unsigned aB = sbase + stw * STAGE, bB = aB + 16384;
            cpa16(swz(aB, r, c0 + 0), aH + k0, av);     cpa16(swz(aB, r, c0 + 1), aH + k0 + 8, av);
            cpa16(swz(aB, r, c0 + 4), aL + k0, av);     cpa16(swz(aB, r, c0 + 5), aL + k0 + 8, av);
            if (bv) {
                cpa16(swz(bB, r, c0 + 0), bH + k0, true);   cpa16(swz(bB, r, c0 + 1), bH + k0 + 8, true);
                cpa16(swz(bB, r, c0 + 4), bL + k0, true);   cpa16(swz(bB, r, c0 + 5), bL + k0 + 8, true);
            }
        }
        cpa_commit();

        const unsigned sA = sbase + st * STAGE, sB = sA + 16384;
#pragma unroll
        for (int ks = 0; ks < 2; ks++) {
            const int kc = ks * 2 + lchk;
            unsigned ah[2][4], al[2][4];
#pragma unroll
            for (int mf = 0; mf < 2; mf++) {
                int row = wm + mf * 16 + lrow;
                ldsm_x4(ah[mf], swz(sA, row, kc));
                ldsm_x4(al[mf], swz(sA, row, kc + 4));
            }
#pragma unroll
            for (int p = 0; p < NP; p++) {
                int row = wn + p * 16 + lrow;
                unsigned bh[4], bl[4];
                ldsm_x4(bh, swz(sB, row, kc));
                ldsm_x4(bl, swz(sB, row, kc + 4));
#pragma unroll
                for (int mf = 0; mf < 2; mf++) {
                    mma_bf16(acc[mf][2 * p],     ah[mf], bh[0], bh[2]);
                    mma_bf16(acc[mf][2 * p],     al[mf], bh[0], bh[2]);
                    mma_bf16(acc[mf][2 * p],     ah[mf], bl[0], bl[2]);
                    mma_bf16(acc[mf][2 * p + 1], ah[mf], bh[1], bh[3]);
                    mma_bf16(acc[mf][2 * p + 1], al[mf], bh[1], bh[3]);
                    mma_bf16(acc[mf][2 * p + 1], ah[mf], bl[1], bl[3]);
                }
            }
        }
        st = (st + 1 == 3) ? 0 : st + 1;
    }

    // epilogue: column pairs (cc even) never straddle the even split/aoff
    // boundaries -> vectorized STG.64 for C1/C2; scalar fallback for alpha.
#pragma unroll
    for (int mf = 0; mf < 2; mf++) {
#pragma unroll
        for (int halfq = 0; halfq < 2; halfq++) {
            int rr = bm + wm + mf * 16 + g + halfq * 8;
            if (rr >= M) continue;
#pragma unroll
            for (int nf = 0; nf < NFR; nf++) {
                int cc = bn + wn + nf * 8 + t2;
                float v0 = acc[mf][nf][halfq * 2 + 0];
                float v1 = acc[mf][nf][halfq * 2 + 1];
                if (cc < split) {
                    *reinterpret_cast<float2*>(&C1[(size_t)rr * ldc1 + cc]) =
                        make_float2(v0, v1);
                } else if (cc < aoff) {
                    int c2 = cc - split;
                    if (bias2) { v0 += bias2[c2]; v1 += bias2[c2 + 1]; }
                    *reinterpret_cast<float2*>(&C2[(size_t)rr * ldc2 + c2]) =
                        make_float2(v0, v1);
                } else {
#pragma unroll
                    for (int q = 0; q < 2; q++) {
                        int c = cc + q;
                        float v = (q == 0) ? v0 : v1;
                        if (c < aoff + nha) {
                            aso[(size_t)rr * nha + (c - aoff)] = v;
                        } else if (c < aoff + 2 * nha) {
                            ado[(size_t)rr * nha + (c - aoff - nha)] = v;
                        }
                    }
                }
            }
        }
    }
}

// ---------------- 8-head aggregation (2-edge unrolled) + BN/ELU/skip; emits hi/lo bf16 ----------------
__global__ void agg8_kernel(const float* __restrict__ h,
                            const float* __restrict__ as_, const float* __restrict__ ad_,
                            const int* __restrict__ rowptr, const int* __restrict__ col,
                            const float* __restrict__ scale, const float* __restrict__ shift,
                            const float* __restrict__ skip,
                            ush* __restrict__ outhi, ush* __restrict__ outlo, int n) {
    int node = (blockIdx.x * blockDim.x + threadIdx.x) >> 5;
    if (node >= n) return;
    int lane = threadIdx.x & 31;
    int hd8 = lane & 7;
    int wsrc = lane >> 2;
    float adv = ad_[(size_t)node * 8 + hd8];
    int start = rowptr[node], end = rowptr[node + 1];
    float acc[8];
#pragma unroll
    for (int i = 0; i < 8; i++) acc[i] = 0.f;
    float denom = 0.f;

    int sA = __ldg(&col[start]);
    float lA = __ldg(&as_[(size_t)sA * 8 + hd8]);
    int sB = 0; float lB = 0.f;
    if (start + 1 < end) {
        sB = __ldg(&col[start + 1]);
        lB = __ldg(&as_[(size_t)sB * 8 + hd8]);
    }
    for (int j = start; j < end; j += 2) {
        int s0 = sA; float e0 = lA;
        bool two = (j + 1 < end);
        int s1 = sB; float e1 = lB;
        if (j + 2 < end) {
            sA = __ldg(&col[j + 2]);
            lA = __ldg(&as_[(size_t)sA * 8 + hd8]);
        }
        if (j + 3 < end) {
            sB = __ldg(&col[j + 3]);
            lB = __ldg(&as_[(size_t)sB * 8 + hd8]);
        }
        e0 += adv; e0 = e0 > 0.f ? e0 : 0.2f * e0;
        float w0 = __expf(e0);
        denom += w0;
        float wh0 = __shfl_sync(FULLMASK, w0, wsrc);
        const float4* hp0 = reinterpret_cast<const float4*>(h + (size_t)s0 * 256 + lane * 8);
        float4 v00 = __ldcg(hp0), v01 = __ldcg(hp0 + 1);
        if (two) {
            e1 += adv; e1 = e1 > 0.f ? e1 : 0.2f * e1;
            float w1 = __expf(e1);
            denom += w1;
            float wh1 = __shfl_sync(FULLMASK, w1, wsrc);
            const float4* hp1 = reinterpret_cast<const float4*>(h + (size_t)s1 * 256 + lane * 8);
            float4 v10 = __ldcg(hp1), v11 = __ldcg(hp1 + 1);
            acc[0] = fmaf(wh0, v00.x, acc[0]); acc[1] = fmaf(wh0, v00.y, acc[1]);
            acc[2] = fmaf(wh0, v00.z, acc[2]); acc[3] = fmaf(wh0, v00.w, acc[3]);
            acc[4] = fmaf(wh0, v01.x, acc[4]); acc[5] = fmaf(wh0, v01.y, acc[5]);
            acc[6] = fmaf(wh0, v01.z, acc[6]); acc[7] = fmaf(wh0, v01.w, acc[7]);
            acc[0] = fmaf(wh1, v10.x, acc[0]); acc[1] = fmaf(wh1, v10.y, acc[1]);
            acc[2] = fmaf(wh1, v10.z, acc[2]); acc[3] = fmaf(wh1, v10.w, acc[3]);
            acc[4] = fmaf(wh1, v11.x, acc[4]); acc[5] = fmaf(wh1, v11.y, acc[5]);
            acc[6] = fmaf(wh1, v11.z, acc[6]); acc[7] = fmaf(wh1, v11.w, acc[7]);
        } else {
            acc[0] = fmaf(wh0, v00.x, acc[0]); acc[1] = fmaf(wh0, v00.y, acc[1]);
            acc[2] = fmaf(wh0, v00.z, acc[2]); acc[3] = fmaf(wh0, v00.w, acc[3]);
            acc[4] = fmaf(wh0, v01.x, acc[4]); acc[5] = fmaf(wh0, v01.y, acc[5]);
            acc[6] = fmaf(wh0, v01.z, acc[6]); acc[7] = fmaf(wh0, v01.w, acc[7]);
        }
    }
    float dh = __shfl_sync(FULLMASK, denom, wsrc) + 1e-16f;
    float inv = 1.f / dh;
    int chb = lane * 8;
    float4 s0v, s1v;
    if (skip) {
        const float4* sp = reinterpret_cast<const float4*>(skip + (size_t)node * 256 + chb);
        s0v = __ldcg(sp); s1v = __ldcg(sp + 1);
    } else {
        s0v = make_float4(0.f, 0.f, 0.f, 0.f); s1v = s0v;
    }
    float sk[8] = {s0v.x, s0v.y, s0v.z, s0v.w, s1v.x, s1v.y, s1v.z, s1v.w};
    ush hv[8], lv[8];
#pragma unroll
    for (int j = 0; j < 8; j++) {
        int ch = chb + j;
        float y = acc[j] * inv;
        y = y * scale[ch] + shift[ch];
        y = y > 0.f ? y : expm1f(y);
        y += sk[j];
        split1(y, hv[j], lv[j]);
    }
    *reinterpret_cast<uint4*>(outhi + (size_t)node * 256 + chb) = *reinterpret_cast<uint4*>(hv);
    *reinterpret_cast<uint4*>(outlo + (size_t)node * 256 + chb) = *reinterpret_cast<uint4*>(lv);
}

// ---------------- 1-head final aggregation + bias + skip ----------------
__global__ void agg1_kernel(const float* __restrict__ h3,
                            const float* __restrict__ as3, const float* __restrict__ ad3,
                            const int* __restrict__ rowptr, const int* __restrict__ col,
                            const float* __restrict__ b3, const float* __restrict__ xs,
                            float* __restrict__ out, int n) {
    int node = (blockIdx.x * blockDim.x + threadIdx.x) >> 5;
    if (node >= n) return;
    int lane = threadIdx.x & 31;
    float adv = ad3[node];
    int start = rowptr[node], end = rowptr[node + 1];
    float acc = 0.f, denom = 0.f;
    int sn = __ldg(&col[start]);
    float an = __ldg(&as3[sn]);
    for (int j = start; j < end; ++j) {
        int s = sn;
        float asv = an;
        if (j + 1 < end) {
            sn = __ldg(&col[j + 1]);
            an = __ldg(&as3[sn]);
        }
        float e = asv + adv;
        e = e > 0.f ? e : 0.2f * e;
        float w = __expf(e);
        denom += w;
        acc = fmaf(w, __ldcg(&h3[(size_t)s * 32 + lane]), acc);
    }
    out[(size_t)node * 32 + lane] = acc / (denom + 1e-16f) + b3[lane] + xs[(size_t)node * 32 + lane];
}

// ---------------- host launcher ----------------
#define GSYM(ptr, sym) do { void* _t; cudaGetSymbolAddress(&_t, sym); ptr = (decltype(ptr))_t; } while (0)

extern "C" void kernel_launch(void* const* d_in, const int* in_sizes, int n_in,
                              void* d_out, int out_size) {
    const float* x      = (const float*)d_in[0];
    const int*   ei     = (const int*)d_in[1];
    const float* W1     = (const float*)d_in[2];
    const float* a_src1 = (const float*)d_in[3];
    const float* a_dst1 = (const float*)d_in[4];
    const float* b1     = (const float*)d_in[5];
    const float* bn1_g  = (const float*)d_in[6];
    const float* bn1_b  = (const float*)d_in[7];
    const float* bn1_m  = (const float*)d_in[8];
    const float* bn1_v  = (const float*)d_in[9];
    const float* W2     = (const float*)d_in[10];
    const float* a_src2 = (const float*)d_in[11];
    const float* a_dst2 = (const float*)d_in[12];
    const float* b2     = (const float*)d_in[13];
    const float* bn2_g  = (const float*)d_in[14];
    const float* bn2_b  = (const float*)d_in[15];
    const float* bn2_m  = (const float*)d_in[16];
    const float* bn2_v  = (const float*)d_in[17];
    const float* W3     = (const float*)d_in[18];
    const float* a_src3 = (const float*)d_in[19];
    const float* a_dst3 = (const float*)d_in[20];
    const float* b3     = (const float*)d_in[21];
    const float* Ws1    = (const float*)d_in[22];
    const float* bs1    = (const float*)d_in[23];
    const float* Ws2    = (const float*)d_in[24];
    const float* bs2    = (const float*)d_in[25];

    const int N = in_sizes[0] / 128;
    const int E = in_sizes[1] / 2;
    const int* srcp = ei;
    const int* dstp = ei + E;

    int *deg, *pos, *rowptr, *col;
    float *h1, *x0, *as_, *ad_, *h2, *xs, *h3, *as3, *ad3;
    float *scale1, *shift1, *scale2, *shift2;
    ush *xhi, *xlo, *o1hi, *o1lo, *o2hi, *o2lo;
    ush *bt1hi, *bt1lo, *bt2hi, *bt2lo, *bt3hi, *bt3lo;
    GSYM(deg, g_deg); GSYM(pos, g_pos); GSYM(rowptr, g_rowptr); GSYM(col, g_col);
    GSYM(h1, g_h1); GSYM(x0, g_x0); GSYM(as_, g_as); GSYM(ad_, g_ad);
    GSYM(h2, g_h2); GSYM(xs, g_xs); GSYM(h3, g_h3); GSYM(as3, g_as3); GSYM(ad3, g_ad3);
    GSYM(scale1, g_scale1); GSYM(shift1, g_shift1);
    GSYM(scale2, g_scale2); GSYM(shift2, g_shift2);
    GSYM(xhi, g_xhi); GSYM(xlo, g_xlo);
    GSYM(o1hi, g_o1hi); GSYM(o1lo, g_o1lo); GSYM(o2hi, g_o2hi); GSYM(o2lo, g_o2lo);
    GSYM(bt1hi, g_bt1hi); GSYM(bt1lo, g_bt1lo);
    GSYM(bt2hi, g_bt2hi); GSYM(bt2lo, g_bt2lo);
    GSYM(bt3hi, g_bt3hi); GSYM(bt3lo, g_bt3lo);

    static cudaStream_t s2 = 0;
    static cudaEvent_t evFork = 0, evP1 = 0, evJ1 = 0, evO1 = 0, evJ2 = 0;
    static bool inited = false;
    if (!inited) {
        cudaFuncSetAttribute(mma_gemm_kernel<128>,
                             cudaFuncAttributeMaxDynamicSharedMemorySize, 3 * 256 * 128);
        cudaFuncSetAttribute(mma_gemm_kernel<64>,
                             cudaFuncAttributeMaxDynamicSharedMemorySize, 3 * 192 * 128);
        cudaStreamCreateWithFlags(&s2, cudaStreamNonBlocking);
        cudaEventCreateWithFlags(&evFork, cudaEventDisableTiming);
        cudaEventCreateWithFlags(&evP1, cudaEventDisableTiming);
        cudaEventCreateWithFlags(&evJ1, cudaEventDisableTiming);
        cudaEventCreateWithFlags(&evO1, cudaEventDisableTiming);
        cudaEventCreateWithFlags(&evJ2, cudaEventDisableTiming);
        inited = true;
    }

    const int TB = 256;
    const int nb_N  = (N + TB - 1) / TB;
    const int nb_E  = (E + TB - 1) / TB;
    const int nb_W  = (N * 32 + TB - 1) / TB;
    const int gy    = (N + 127) / 128;

    // ---- fork ----
    cudaEventRecord(evFork, 0);
    cudaStreamWaitEvent(s2, evFork, 0);

    // side stream: CSR + bnprep + packs 2/3
    init_deg_kernel<<<nb_N, TB, 0, s2>>>(deg, N);
    count_kernel<<<nb_E, TB, 0, s2>>>(dstp, E, deg);
    scan_kernel<<<1, 1024, 0, s2>>>(deg, rowptr, N);
    selfscatter_kernel<<<nb_N, TB, 0, s2>>>(rowptr, col, pos, N);
    scatter_kernel<<<nb_E, TB, 0, s2>>>(srcp, dstp, E, pos, col);
    bnprep_kernel<<<1, 256, 0, s2>>>(b1, bn1_g, bn1_b, bn1_m, bn1_v,
                                     b2, bn2_g, bn2_b, bn2_m, bn2_v);
    pack_bt_kernel<<<(384 * 256 + TB - 1) / TB, TB, 0, s2>>>(W2, 256, 256, Ws2, 32, 32,
                                                             a_src2, a_dst2, 8, 256, 384, bt2hi, bt2lo);
    pack_bt_kernel<<<(64 * 256 + TB - 1) / TB, TB, 0, s2>>>(W3, 32, 32, W3, 32, 0,
                                                            a_src3, a_dst3, 1, 256, 64, bt3hi, bt3lo);

    // main: converts + pack1
    convert_x_kernel<<<(N * 128 / 4 + TB - 1) / TB, TB>>>(x, xhi, xlo, N * 128 / 4);
    pack_bt_kernel<<<(640 * 128 + TB - 1) / TB, TB>>>(W1, 256, 256, Ws1, 256, 256,
                                                      a_src1, a_dst1, 8, 128, 640, bt1hi, bt1lo);
    cudaEventRecord(evP1, 0);

    // GEMM1 main (h1 | x0+bs1), tail (alpha1) overlapped on s2
    mma_gemm_kernel<128><<<dim3(4, gy), TB, 3 * 256 * 128>>>(xhi, xlo, N, 128, bt1hi, bt1lo,
                                                             0, 256, 512, 8,
                                                             h1, 256, x0, 256, bs1, as_, ad_);
    cudaStreamWaitEvent(s2, evP1, 0);
    mma_gemm_kernel<64><<<dim3(1, gy), TB, 3 * 192 * 128, s2>>>(xhi, xlo, N, 128, bt1hi, bt1lo,
                                                                512, 0, 512, 8,
                                                                h1, 256, x0, 256, bs1, as_, ad_);
    cudaEventRecord(evJ1, s2);
    cudaStreamWaitEvent(0, evJ1, 0);

    // layer-1 aggregation
    agg8_kernel<<<nb_W, TB>>>(h1, as_, ad_, rowptr, col, scale1, shift1, x0, o1hi, o1lo, N);
    cudaEventRecord(evO1, 0);

    // GEMM2 main (h2 cols 0-255); tail (xs + alpha2) on s2 overlapped
    mma_gemm_kernel<128><<<dim3(2, gy), TB, 3 * 256 * 128>>>(o1hi, o1lo, N, 256, bt2hi, bt2lo,
                                                             0, 256, 288, 8,
                                                             h2, 256, xs, 32, bs2, as_, ad_);
    cudaStreamWaitEvent(s2, evO1, 0);
    mma_gemm_kernel<64><<<dim3(1, gy), TB, 3 * 192 * 128, s2>>>(o1hi, o1lo, N, 256, bt2hi, bt2lo,
                                                                256, 256, 288, 8,
                                                                h2, 256, xs, 32, bs2, as_, ad_);
    cudaEventRecord(evJ2, s2);
    cudaStreamWaitEvent(0, evJ2, 0);

    agg8_kernel<<<nb_W, TB>>>(h2, as_, ad_, rowptr, col, scale2, shift2, nullptr, o2hi, o2lo, N);

    // layer 3 (h3 | alpha_s3 | alpha_d3), narrow BN=64 tile
    mma_gemm_kernel<64><<<dim3(1, gy), TB, 3 * 192 * 128>>>(o2hi, o2lo, N, 256, bt3hi, bt3lo,
                                                            0, 32, 32, 1,
                                                            h3, 32, h3, 32, nullptr, as3, ad3);
    agg1_kernel<<<nb_W, TB>>>(h3, as3, ad3, rowptr, col, b3, xs, (float*)d_out, N);
}

// round 16
// speedup vs baseline: 1.4630x; 1.0024x over previous
#include <cuda_runtime.h>
#include <cuda_bf16.h>
#include <math.h>

#define NN 50000
#define EE 800000
#define FULLMASK 0xffffffffu
typedef unsigned short ush;

// ---------------- scratch (static device memory; no allocations) ----------------
__device__ int   g_deg[NN];
__device__ int   g_pos[NN];
__device__ int   g_rowptr[NN + 1];
__device__ int   g_col[EE + NN];
__device__ float g_h1[NN * 256];
__device__ float g_x0[NN * 256];
__device__ float g_as[NN * 8];
__device__ float g_ad[NN * 8];
__device__ float g_h2[NN * 256];
__device__ float g_xs[NN * 32];
__device__ float g_h3[NN * 32];
__device__ float g_as3[NN];
__device__ float g_ad3[NN];
__device__ float g_scale1[256], g_shift1[256], g_scale2[256], g_shift2[256];
// pre-split bf16 operands
__device__ ush g_xhi[NN * 128],  g_xlo[NN * 128];
__device__ ush g_o1hi[NN * 256], g_o1lo[NN * 256];
__device__ ush g_o2hi[NN * 256], g_o2lo[NN * 256];
__device__ ush g_bt1hi[640 * 128], g_bt1lo[640 * 128];   // [W1|Ws1|va1] pad->640, K=128
__device__ ush g_bt2hi[384 * 256], g_bt2lo[384 * 256];   // [W2|Ws2|va2] pad->384, K=256
__device__ ush g_bt3hi[64 * 256],  g_bt3lo[64 * 256];    // [W3|va3]     pad->64,  K=256

__device__ __forceinline__ void split1(float f, ush& h, ush& l) {
    __nv_bfloat16 hb = __float2bfloat16(f);
    h = __bfloat16_as_ushort(hb);
    l = __bfloat16_as_ushort(__float2bfloat16(f - __bfloat162float(hb)));
}

// ---------------- CSR build ----------------
__global__ void init_deg_kernel(int* deg, int n) {
    int i = blockIdx.x * blockDim.x + threadIdx.x;
    if (i < n) deg[i] = 1;
}

__global__ void count_kernel(const int* __restrict__ dst, int e, int* __restrict__ deg) {
    int i = blockIdx.x * blockDim.x + threadIdx.x;
    if (i < e) atomicAdd(&deg[dst[i]], 1);
}

__global__ void scan_kernel(const int* __restrict__ deg, int* __restrict__ rowptr, int n) {
    __shared__ int wsum[32];
    __shared__ int s_carry;
    int tid = threadIdx.x, lane = tid & 31, wid = tid >> 5;
    if (tid == 0) { s_carry = 0; rowptr[0] = 0; }
    __syncthreads();
    for (int base = 0; base < n; base += 4096) {
        int i = base + tid * 4;
        int v0 = (i     < n) ? deg[i]     : 0;
        int v1 = (i + 1 < n) ? deg[i + 1] : 0;
        int v2 = (i + 2 < n) ? deg[i + 2] : 0;
        int v3 = (i + 3 < n) ? deg[i + 3] : 0;
        int s = v0 + v1 + v2 + v3;
        int inc = s;
#pragma unroll
        for (int off = 1; off < 32; off <<= 1) {
            int t = __shfl_up_sync(FULLMASK, inc, off);
            if (lane >= off) inc += t;
        }
        if (lane == 31) wsum[wid] = inc;
        __syncthreads();
        if (wid == 0) {
            int w = wsum[lane];
#pragma unroll
            for (int off = 1; off < 32; off <<= 1) {
                int t = __shfl_up_sync(FULLMASK, w, off);
                if (lane >= off) w += t;
            }
            wsum[lane] = w;
        }
        __syncthreads();
        int excl = s_carry + (wid ? wsum[wid - 1] : 0) + (inc - s);
        if (i     < n) rowptr[i + 1] = excl + v0;
        if (i + 1 < n) rowptr[i + 2] = excl + v0 + v1;
        if (i + 2 < n) rowptr[i + 3] = excl + v0 + v1 + v2;
        if (i + 3 < n) rowptr[i + 4] = excl + s;
        __syncthreads();
        if (tid == 0) s_carry += wsum[31];
        __syncthreads();
    }
}

__global__ void selfscatter_kernel(const int* __restrict__ rowptr, int* __restrict__ col,
                                   int* __restrict__ pos, int n) {
    int i = blockIdx.x * blockDim.x + threadIdx.x;
    if (i < n) {
        int r = rowptr[i];
        col[r] = i;
        pos[i] = r + 1;
    }
}

__global__ void scatter_kernel(const int* __restrict__ src, const int* __restrict__ dst, int e,
                               int* __restrict__ pos, int* __restrict__ col) {
    int i = blockIdx.x * blockDim.x + threadIdx.x;
    if (i < e) {
        int d = dst[i];
        int p = atomicAdd(&pos[d], 1);
        col[p] = src[i];
    }
}

// ---------------- BN fold ----------------
__global__ void bnprep_kernel(const float* b1, const float* g1, const float* be1,
                              const float* m1, const float* v1,
                              const float* b2, const float* g2, const float* be2,
                              const float* m2, const float* v2) {
    int t = threadIdx.x;
    if (t < 256) {
        float s1 = g1[t] * rsqrtf(v1[t] + 1e-5f);
        g_scale1[t] = s1;
        g_shift1[t] = be1[t] + (b1[t] - m1[t]) * s1;
        float s2 = g2[t] * rsqrtf(v2[t] + 1e-5f);
        g_scale2[t] = s2;
        g_shift2[t] = be2[t] + (b2[t] - m2[t]) * s2;
    }
}

// ---------------- pre-split converts ----------------
__global__ void convert_x_kernel(const float* __restrict__ x, ush* __restrict__ hi,
                                 ush* __restrict__ lo, int total4) {
    int i = blockIdx.x * blockDim.x + threadIdx.x;
    if (i >= total4) return;
    float4 v = *reinterpret_cast<const float4*>(x + i * 4);
    ush h[4], l[4];
    split1(v.x, h[0], l[0]); split1(v.y, h[1], l[1]);
    split1(v.z, h[2], l[2]); split1(v.w, h[3], l[3]);
    *reinterpret_cast<uint2*>(hi + i * 4) = *reinterpret_cast<uint2*>(h);
    *reinterpret_cast<uint2*>(lo + i * 4) = *reinterpret_cast<uint2*>(l);
}

// pack [B1 | B2 | v_src | v_dst]^T into [colPad][K] hi/lo.
__global__ void pack_bt_kernel(const float* __restrict__ B1, int ldb1, int w1,
                               const float* __restrict__ B2, int ldb2, int w2,
                               const float* __restrict__ aS, const float* __restrict__ aD,
                               int nha,
                               int K, int colPad, ush* __restrict__ hi, ush* __restrict__ lo) {
    int i = blockIdx.x * blockDim.x + threadIdx.x;
    if (i >= colPad * K) return;
    int c = i / K, k = i - c * K;
    float v = 0.f;
    if (c < w1) {
        v = B1[(size_t)k * ldb1 + c];
    } else if (c < w1 + w2) {
        v = B2[(size_t)k * ldb2 + (c - w1)];
    } else if (c < w1 + w2 + 2 * nha) {
        int j = c - w1 - w2;
        const float* av = (j < nha) ? aS : aD;
        int hh = j % nha;
        const float* wrow = B1 + (size_t)k * ldb1 + hh * 32;
        const float* arow = av + hh * 32;
        float s = 0.f;
#pragma unroll 8
        for (int cc = 0; cc < 32; cc++) s += wrow[cc] * arow[cc];
        v = s;
    }
    split1(v, hi[i], lo[i]);
}

// ---------------- tensor-core GEMM: 3-stage cp.async, pre-split bf16 ----------------
__device__ __forceinline__ void mma_bf16(float* c, const unsigned* a, unsigned b0, unsigned b1) {
    asm volatile(
        "mma.sync.aligned.m16n8k16.row.col.f32.bf16.bf16.f32 "
        "{%0,%1,%2,%3}, {%4,%5,%6,%7}, {%8,%9}, {%0,%1,%2,%3};"
        : "+f"(c[0]), "+f"(c[1]), "+f"(c[2]), "+f"(c[3])
        : "r"(a[0]), "r"(a[1]), "r"(a[2]), "r"(a[3]), "r"(b0), "r"(b1));
}

__device__ __forceinline__ void ldsm_x4(unsigned* r, unsigned addr) {
    asm volatile("ldmatrix.sync.aligned.m8n8.x4.shared.b16 {%0,%1,%2,%3}, [%4];"
                 : "=r"(r[0]), "=r"(r[1]), "=r"(r[2]), "=r"(r[3]) : "r"(addr));
}

__device__ __forceinline__ void cpa16(unsigned dst, const void* src, bool valid) {
    int sz = valid ? 16 : 0;
    asm volatile("cp.async.cg.shared.global [%0], [%1], 16, %2;"
                 :: "r"(dst), "l"(src), "r"(sz));
}
__device__ __forceinline__ void cpa_commit() {
    asm volatile("cp.async.commit_group;" ::: "memory");
}
template <int Nw>
__device__ __forceinline__ void cpa_wait() {
    asm volatile("cp.async.wait_group %0;" :: "n"(Nw) : "memory");
}

// row layout: 128B/row, 8x16B chunks (0-3 hi k0..31, 4-7 lo). phys = chunk ^ (row&7)
__device__ __forceinline__ unsigned swz(unsigned base, int row, int chunk) {
    return base + row * 128 + ((chunk ^ (row & 7)) << 4);
}

// C = A @ [B1|B2|vS|vD]. Cols bnbase + blockIdx.x*BN. Routing per column-pair.
template <int BN>
__global__ void __launch_bounds__(256, 2)
mma_gemm_kernel(const ush* __restrict__ Ahi, const ush* __restrict__ Alo, int M, int K,
                const ush* __restrict__ Bthi, const ush* __restrict__ Btlo,
                int bnbase,
                int split, int aoff, int nha,
                float* __restrict__ C1, int ldc1,
                float* __restrict__ C2, int ldc2,
                const float* __restrict__ bias2,
                float* __restrict__ aso, float* __restrict__ ado) {
    constexpr int NFR   = BN / 16;
    constexpr int NP    = BN / 32;
    constexpr int STAGE = (128 + BN) * 128;
    extern __shared__ __align__(16) unsigned char smem[];
    const unsigned sbase = (unsigned)__cvta_generic_to_shared(smem);

    const int tid  = threadIdx.x;
    const int lane = tid & 31, warp = tid >> 5;
    const int wm = (warp & 3) * 32;
    const int wn = (warp >> 2) * (BN / 2);
    const int g  = lane >> 2, t2 = (lane & 3) * 2;
    const int bm = blockIdx.y * 128, bn = bnbase + blockIdx.x * BN;
    const int lrow = lane & 15, lchk = lane >> 4;

    const int r = tid >> 1, half = tid & 1;
    const int gr = bm + r;
    const bool av = gr < M;
    const bool bv = tid < 2 * BN;
    const ush* aH = Ahi + (size_t)(av ? gr : 0) * K + half * 16;
    const ush* aL = Alo + (size_t)(av ? gr : 0) * K + half * 16;
    const ush* bH = Bthi + (size_t)(bn + (bv ? r : 0)) * K + half * 16;
    const ush* bL = Btlo + (size_t)(bn + (bv ? r : 0)) * K + half * 16;
    const int c0 = half * 2;

    float acc[2][NFR][4];
#pragma unroll
    for (int mf = 0; mf < 2; mf++)
#pragma unroll
        for (int nf = 0; nf < NFR; nf++)
#pragma unroll
            for (int q = 0; q < 4; q++) acc[mf][nf][q] = 0.f;

    const int niter = K >> 5;

#pragma unroll
    for (int pstg = 0; pstg < 2; pstg++) {
        if (pstg < niter) {
            int k0 = pstg << 5;
            unsigned aB = sbase + pstg * STAGE, bB = aB + 16384;
            cpa16(swz(aB, r, c0 + 0), aH + k0, av);     cpa16(swz(aB, r, c0 + 1), aH + k0 + 8, av);
            cpa16(swz(aB, r, c0 + 4), aL + k0, av);     cpa16(swz(aB, r, c0 + 5), aL + k0 + 8, av);
            if (bv) {
                cpa16(swz(bB, r, c0 + 0), bH + k0, true);   cpa16(swz(bB, r, c0 + 1), bH + k0 + 8, true);
                cpa16(swz(bB, r, c0 + 4), bL + k0, true);   cpa16(swz(bB, r, c0 + 5), bL + k0 + 8, true);
            }
        }
        cpa_commit();
    }

    int st = 0;
    for (int i = 0; i < niter; i++) {
        cpa_wait<1>();
        __syncthreads();
        int stw = st + 2; if (stw >= 3) stw -= 3;
        if (i + 2 < niter) {
            int k0 = (i + 2) << 5;
            unsigned aB = sbase + stw * STAGE, bB = aB + 16384;
            cpa16(swz(aB, r, c0 + 0), aH + k0, av);     cpa16(swz(aB, r, c0 + 1), aH + k0 + 8, av);
            cpa16(swz(aB, r, c0 + 4), aL + k0, av);     cpa16(swz(aB, r, c0 + 5), aL + k0 + 8, av);
            if (bv) {
                cpa16(swz(bB, r, c0 + 0), bH + k0, true);   cpa16(swz(bB, r, c0 + 1), bH + k0 + 8, true);
                cpa16(swz(bB, r, c0 + 4), bL + k0, true);   cpa16(swz(bB, r, c0 + 5), bL + k0 + 8, true);
            }
        }
        cpa_commit();

        const unsigned sA = sbase + st * STAGE, sB = sA + 16384;
#pragma unroll
        for (int ks = 0; ks < 2; ks++) {
            const int kc = ks * 2 + lchk;
            unsigned ah[2][4], al[2][4];
#pragma unroll
            for (int mf = 0; mf < 2; mf++) {
                int row = wm + mf * 16 + lrow;
                ldsm_x4(ah[mf], swz(sA, row, kc));
                ldsm_x4(al[mf], swz(sA, row, kc + 4));
            }
#pragma unroll
            for (int p = 0; p < NP; p++) {
                int row = wn + p * 16 + lrow;
                unsigned bh[4], bl[4];
                ldsm_x4(bh, swz(sB, row, kc));
                ldsm_x4(bl, swz(sB, row, kc + 4));
#pragma unroll
                for (int mf = 0; mf < 2; mf++) {
                    mma_bf16(acc[mf][2 * p],     ah[mf], bh[0], bh[2]);
                    mma_bf16(acc[mf][2 * p],     al[mf], bh[0], bh[2]);
                    mma_bf16(acc[mf][2 * p],     ah[mf], bl[0], bl[2]);
                    mma_bf16(acc[mf][2 * p + 1], ah[mf], bh[1], bh[3]);
                    mma_bf16(acc[mf][2 * p + 1], al[mf], bh[1], bh[3]);
                    mma_bf16(acc[mf][2 * p + 1], ah[mf], bl[1], bl[3]);
                }
            }
        }
        st = (st + 1 == 3) ? 0 : st + 1;
    }

    // epilogue: column pairs (cc even) never straddle the even split/aoff
    // boundaries -> vectorized STG.64 for C1/C2; scalar fallback for alpha.
#pragma unroll
    for (int mf = 0; mf < 2; mf++) {
#pragma unroll
        for (int halfq = 0; halfq < 2; halfq++) {
            int rr = bm + wm + mf * 16 + g + halfq * 8;
            if (rr >= M) continue;
#pragma unroll
            for (int nf = 0; nf < NFR; nf++) {
                int cc = bn + wn + nf * 8 + t2;
                float v0 = acc[mf][nf][halfq * 2 + 0];
                float v1 = acc[mf][nf][halfq * 2 + 1];
                if (cc < split) {
                    *reinterpret_cast<float2*>(&C1[(size_t)rr * ldc1 + cc]) =
                        make_float2(v0, v1);
                } else if (cc < aoff) {
                    int c2 = cc - split;
                    if (bias2) { v0 += bias2[c2]; v1 += bias2[c2 + 1]; }
                    *reinterpret_cast<float2*>(&C2[(size_t)rr * ldc2 + c2]) =
                        make_float2(v0, v1);
                } else {
#pragma unroll
                    for (int q = 0; q < 2; q++) {
                        int c = cc + q;
                        float v = (q == 0) ? v0 : v1;
                        if (c < aoff + nha) {
                            aso[(size_t)rr * nha + (c - aoff)] = v;
                        } else if (c < aoff + 2 * nha) {
                            ado[(size_t)rr * nha + (c - aoff - nha)] = v;
                        }
                    }
                }
            }
        }
    }
}

// ---------------- 8-head aggregation (2-edge unrolled) + BN/ELU/skip; emits hi/lo bf16 ----------------
__global__ void agg8_kernel(const float* __restrict__ h,
                            const float* __restrict__ as_, const float* __restrict__ ad_,
                            const int* __restrict__ rowptr, const int* __restrict__ col,
                            const float* __restrict__ scale, const float* __restrict__ shift,
                            const float* __restrict__ skip,
                            ush* __restrict__ outhi, ush* __restrict__ outlo, int n) {
    int node = (blockIdx.x * blockDim.x + threadIdx.x) >> 5;
    if (node >= n) return;
    int lane = threadIdx.x & 31;
    int hd8 = lane & 7;
    int wsrc = lane >> 2;
    float adv = ad_[(size_t)node * 8 + hd8];
    int start = rowptr[node], end = rowptr[node + 1];
    float acc[8];
#pragma unroll
    for (int i = 0; i < 8; i++) acc[i] = 0.f;
    float denom = 0.f;

    int sA = __ldg(&col[start]);
    float lA = __ldg(&as_[(size_t)sA * 8 + hd8]);
    int sB = 0; float lB = 0.f;
    if (start + 1 < end) {
        sB = __ldg(&col[start + 1]);
        lB = __ldg(&as_[(size_t)sB * 8 + hd8]);
    }
    for (int j = start; j < end; j += 2) {
        int s0 = sA; float e0 = lA;
        bool two = (j + 1 < end);
        int s1 = sB; float e1 = lB;
        if (j + 2 < end) {
            sA = __ldg(&col[j + 2]);
            lA = __ldg(&as_[(size_t)sA * 8 + hd8]);
        }
        if (j + 3 < end) {
            sB = __ldg(&col[j + 3]);
            lB = __ldg(&as_[(size_t)sB * 8 + hd8]);
        }
        e0 += adv; e0 = e0 > 0.f ? e0 : 0.2f * e0;
        float w0 = __expf(e0);
        denom += w0;
        float wh0 = __shfl_sync(FULLMASK, w0, wsrc);
        const float4* hp0 = reinterpret_cast<const float4*>(h + (size_t)s0 * 256 + lane * 8);
        float4 v00 = __ldcg(hp0), v01 = __ldcg(hp0 + 1);
        if (two) {
            e1 += adv; e1 = e1 > 0.f ? e1 : 0.2f * e1;
            float w1 = __expf(e1);
            denom += w1;
            float wh1 = __shfl_sync(FULLMASK, w1, wsrc);
            const float4* hp1 = reinterpret_cast<const float4*>(h + (size_t)s1 * 256 + lane * 8);
            float4 v10 = __ldcg(hp1), v11 = __ldcg(hp1 + 1);
            acc[0] = fmaf(wh0, v00.x, acc[0]); acc[1] = fmaf(wh0, v00.y, acc[1]);
            acc[2] = fmaf(wh0, v00.z, acc[2]); acc[3] = fmaf(wh0, v00.w, acc[3]);
            acc[4] = fmaf(wh0, v01.x, acc[4]); acc[5] = fmaf(wh0, v01.y, acc[5]);
            acc[6] = fmaf(wh0, v01.z, acc[6]); acc[7] = fmaf(wh0, v01.w, acc[7]);
            acc[0] = fmaf(wh1, v10.x, acc[0]); acc[1] = fmaf(wh1, v10.y, acc[1]);
            acc[2] = fmaf(wh1, v10.z, acc[2]); acc[3] = fmaf(wh1, v10.w, acc[3]);
            acc[4] = fmaf(wh1, v11.x, acc[4]); acc[5] = fmaf(wh1, v11.y, acc[5]);
            acc[6] = fmaf(wh1, v11.z, acc[6]); acc[7] = fmaf(wh1, v11.w, acc[7]);
        } else {
            acc[0] = fmaf(wh0, v00.x, acc[0]); acc[1] = fmaf(wh0, v00.y, acc[1]);
            acc[2] = fmaf(wh0, v00.z, acc[2]); acc[3] = fmaf(wh0, v00.w, acc[3]);
            acc[4] = fmaf(wh0, v01.x, acc[4]); acc[5] = fmaf(wh0, v01.y, acc[5]);
            acc[6] = fmaf(wh0, v01.z, acc[6]); acc[7] = fmaf(wh0, v01.w, acc[7]);
        }
    }
    float dh = __shfl_sync(FULLMASK, denom, wsrc) + 1e-16f;
    float inv = 1.f / dh;
    int chb = lane * 8;
    float4 s0v, s1v;
    if (skip) {
        const float4* sp = reinterpret_cast<const float4*>(skip + (size_t)node * 256 + chb);
        s0v = __ldcg(sp); s1v = __ldcg(sp + 1);
    } else {
        s0v = make_float4(0.f, 0.f, 0.f, 0.f); s1v = s0v;
    }
    float sk[8] = {s0v.x, s0v.y, s0v.z, s0v.w, s1v.x, s1v.y, s1v.z, s1v.w};
    ush hv[8], lv[8];
#pragma unroll
    for (int j = 0; j < 8; j++) {
        int ch = chb + j;
        float y = acc[j] * inv;
        y = y * scale[ch] + shift[ch];
        y = y > 0.f ? y : expm1f(y);
        y += sk[j];
        split1(y, hv[j], lv[j]);
    }
    *reinterpret_cast<uint4*>(outhi + (size_t)node * 256 + chb) = *reinterpret_cast<uint4*>(hv);
    *reinterpret_cast<uint4*>(outlo + (size_t)node * 256 + chb) = *reinterpret_cast<uint4*>(lv);
}

// ---------------- 1-head final aggregation + bias + skip ----------------
__global__ void agg1_kernel(const float* __restrict__ h3,
                            const float* __restrict__ as3, const float* __restrict__ ad3,
                            const int* __restrict__ rowptr, const int* __restrict__ col,
                            const float* __restrict__ b3, const float* __restrict__ xs,
                            float* __restrict__ out, int n) {
    int node = (blockIdx.x * blockDim.x + threadIdx.x) >> 5;
    if (node >= n) return;
    int lane = threadIdx.x & 31;
    float adv = ad3[node];
    int start = rowptr[node], end = rowptr[node + 1];
    float acc = 0.f, denom = 0.f;
    int sn = __ldg(&col[start]);
    float an = __ldg(&as3[sn]);
    for (int j = start; j < end; ++j) {
        int s = sn;
        float asv = an;
        if (j + 1 < end) {
            sn = __ldg(&col[j + 1]);
            an = __ldg(&as3[sn]);
        }
        float e = asv + adv;
        e = e > 0.f ? e : 0.2f * e;
        float w = __expf(e);
        denom += w;
        acc = fmaf(w, __ldcg(&h3[(size_t)s * 32 + lane]), acc);
    }
    out[(size_t)node * 32 + lane] = acc / (denom + 1e-16f) + b3[lane] + xs[(size_t)node * 32 + lane];
}

// ---------------- host launcher ----------------
#define GSYM(ptr, sym) do { void* _t; cudaGetSymbolAddress(&_t, sym); ptr = (decltype(ptr))_t; } while (0)

extern "C" void kernel_launch(void* const* d_in, const int* in_sizes, int n_in,
                              void* d_out, int out_size) {
    const float* x      = (const float*)d_in[0];
    const int*   ei     = (const int*)d_in[1];
    const float* W1     = (const float*)d_in[2];
    const float* a_src1 = (const float*)d_in[3];
    const float* a_dst1 = (const float*)d_in[4];
    const float* b1     = (const float*)d_in[5];
    const float* bn1_g  = (const float*)d_in[6];
    const float* bn1_b  = (const float*)d_in[7];
    const float* bn1_m  = (const float*)d_in[8];
    const float* bn1_v  = (const float*)d_in[9];
    const float* W2     = (const float*)d_in[10];
    const float* a_src2 = (const float*)d_in[11];
    const float* a_dst2 = (const float*)d_in[12];
    const float* b2     = (const float*)d_in[13];
    const float* bn2_g  = (const float*)d_in[14];
    const float* bn2_b  = (const float*)d_in[15];
    const float* bn2_m  = (const float*)d_in[16];
    const float* bn2_v  = (const float*)d_in[17];
    const float* W3     = (const float*)d_in[18];
    const float* a_src3 = (const float*)d_in[19];
    const float* a_dst3 = (const float*)d_in[20];
    const float* b3     = (const float*)d_in[21];
    const float* Ws1    = (const float*)d_in[22];
    const float* bs1    = (const float*)d_in[23];
    const float* Ws2    = (const float*)d_in[24];
    const float* bs2    = (const float*)d_in[25];

    const int N = in_sizes[0] / 128;
    const int E = in_sizes[1] / 2;
    const int* srcp = ei;
    const int* dstp = ei + E;

    int *deg, *pos, *rowptr, *col;
    float *h1, *x0, *as_, *ad_, *h2, *xs, *h3, *as3, *ad3;
    float *scale1, *shift1, *scale2, *shift2;
    ush *xhi, *xlo, *o1hi, *o1lo, *o2hi, *o2lo;
    ush *bt1hi, *bt1lo, *bt2hi, *bt2lo, *bt3hi, *bt3lo;
    GSYM(deg, g_deg); GSYM(pos, g_pos); GSYM(rowptr, g_rowptr); GSYM(col, g_col);
    GSYM(h1, g_h1); GSYM(x0, g_x0); GSYM(as_, g_as); GSYM(ad_, g_ad);
    GSYM(h2, g_h2); GSYM(xs, g_xs); GSYM(h3, g_h3); GSYM(as3, g_as3); GSYM(ad3, g_ad3);
    GSYM(scale1, g_scale1); GSYM(shift1, g_shift1);
    GSYM(scale2, g_scale2); GSYM(shift2, g_shift2);
    GSYM(xhi, g_xhi); GSYM(xlo, g_xlo);
    GSYM(o1hi, g_o1hi); GSYM(o1lo, g_o1lo); GSYM(o2hi, g_o2hi); GSYM(o2lo, g_o2lo);
    GSYM(bt1hi, g_bt1hi); GSYM(bt1lo, g_bt1lo);
    GSYM(bt2hi, g_bt2hi); GSYM(bt2lo, g_bt2lo);
    GSYM(bt3hi, g_bt3hi); GSYM(bt3lo, g_bt3lo);

    static cudaStream_t s2 = 0;
    static cudaEvent_t evFork = 0, evP1 = 0, evJ1 = 0, evO1 = 0, evJ2 = 0;
    static bool inited = false;
    if (!inited) {
        cudaFuncSetAttribute(mma_gemm_kernel<128>,
                             cudaFuncAttributeMaxDynamicSharedMemorySize, 3 * 256 * 128);
        cudaFuncSetAttribute(mma_gemm_kernel<64>,
                             cudaFuncAttributeMaxDynamicSharedMemorySize, 3 * 192 * 128);
        cudaStreamCreateWithFlags(&s2, cudaStreamNonBlocking);
        cudaEventCreateWithFlags(&evFork, cudaEventDisableTiming);
        cudaEventCreateWithFlags(&evP1, cudaEventDisableTiming);
        cudaEventCreateWithFlags(&evJ1, cudaEventDisableTiming);
        cudaEventCreateWithFlags(&evO1, cudaEventDisableTiming);
        cudaEventCreateWithFlags(&evJ2, cudaEventDisableTiming);
        inited = true;
    }

    const int TB = 256;
    const int nb_N  = (N + TB - 1) / TB;
    const int nb_E  = (E + TB - 1) / TB;
    const int nb_W  = (N * 32 + TB - 1) / TB;
    const int gy    = (N + 127) / 128;

    // ---- fork ----
    cudaEventRecord(evFork, 0);
    cudaStreamWaitEvent(s2, evFork, 0);

    // side stream: CSR + bnprep + packs 2/3
    init_deg_kernel<<<nb_N, TB, 0, s2>>>(deg, N);
    count_kernel<<<nb_E, TB, 0, s2>>>(dstp, E, deg);
    scan_kernel<<<1, 1024, 0, s2>>>(deg, rowptr, N);
    selfscatter_kernel<<<nb_N, TB, 0, s2>>>(rowptr, col, pos, N);
    scatter_kernel<<<nb_E, TB, 0, s2>>>(srcp, dstp, E, pos, col);
    bnprep_kernel<<<1, 256, 0, s2>>>(b1, bn1_g, bn1_b, bn1_m, bn1_v,
                                     b2, bn2_g, bn2_b, bn2_m, bn2_v);
    pack_bt_kernel<<<(384 * 256 + TB - 1) / TB, TB, 0, s2>>>(W2, 256, 256, Ws2, 32, 32,
                                                             a_src2, a_dst2, 8, 256, 384, bt2hi, bt2lo);
    pack_bt_kernel<<<(64 * 256 + TB - 1) / TB, TB, 0, s2>>>(W3, 32, 32, W3, 32, 0,
                                                            a_src3, a_dst3, 1, 256, 64, bt3hi, bt3lo);

    // main: converts + pack1
    convert_x_kernel<<<(N * 128 / 4 + TB - 1) / TB, TB>>>(x, xhi, xlo, N * 128 / 4);
    pack_bt_kernel<<<(640 * 128 + TB - 1) / TB, TB>>>(W1, 256, 256, Ws1, 256, 256,
                                                      a_src1, a_dst1, 8, 128, 640, bt1hi, bt1lo);
    cudaEventRecord(evP1, 0);

    // GEMM1 main (h1 | x0+bs1), tail (alpha1) overlapped on s2
    mma_gemm_kernel<128><<<dim3(4, gy), TB, 3 * 256 * 128>>>(xhi, xlo, N, 128, bt1hi, bt1lo,
                                                             0, 256, 512, 8,
                                                             h1, 256, x0, 256, bs1, as_, ad_);
    cudaStreamWaitEvent(s2, evP1, 0);
    mma_gemm_kernel<64><<<dim3(1, gy), TB, 3 * 192 * 128, s2>>>(xhi, xlo, N, 128, bt1hi, bt1lo,
                                                                512, 0, 512, 8,
                                                                h1, 256, x0, 256, bs1, as_, ad_);
    cudaEventRecord(evJ1, s2);
    cudaStreamWaitEvent(0, evJ1, 0);

    // layer-1 aggregation
    agg8_kernel<<<nb_W, TB>>>(h1, as_, ad_, rowptr, col, scale1, shift1, x0, o1hi, o1lo, N);
    cudaEventRecord(evO1, 0);

    // GEMM2 main (h2 cols 0-255); tail (xs + alpha2) on s2 overlapped
    mma_gemm_kernel<128><<<dim3(2, gy), TB, 3 * 256 * 128>>>(o1hi, o1lo, N, 256, bt2hi, bt2lo,
                                                             0, 256, 288, 8,
                                                             h2, 256, xs, 32, bs2, as_, ad_);
    cudaStreamWaitEvent(s2, evO1, 0);
    mma_gemm_kernel<64><<<dim3(1, gy), TB, 3 * 192 * 128, s2>>>(o1hi, o1lo, N, 256, bt2hi, bt2lo,
                                                                256, 256, 288, 8,
                                                                h2, 256, xs, 32, bs2, as_, ad_);
    cudaEventRecord(evJ2, s2);
    cudaStreamWaitEvent(0, evJ2, 0);

    agg8_kernel<<<nb_W, TB>>>(h2, as_, ad_, rowptr, col, scale2, shift2, nullptr, o2hi, o2lo, N);

    // layer 3 (h3 | alpha_s3 | alpha_d3), narrow BN=64 tile
    mma_gemm_kernel<64><<<dim3(1, gy), TB, 3 * 192 * 128>>>(o2hi, o2lo, N, 256, bt3hi, bt3lo,
                                                            0, 32, 32, 1,
                                                            h3, 32, h3, 32, nullptr, as3, ad3);
    agg1_kernel<<<nb_W, TB>>>(h3, as3, ad3, rowptr, col, b3, xs, (float*)d_out, N);
}